// round 11
// baseline (speedup 1.0000x reference)
#include <cuda_runtime.h>

#define PH    7
#define PP    49          // PH*PH
#define MB    8
#define NCH   256
#define NBOX  1024
#define CGRP  64          // channels per block (grid.y = NCH/CGRP)
#define SMEMF 11776       // 46 KB staging buffer (floats) -- keep static smem < 48 KB

__global__ __launch_bounds__(256)
void roipool_kernel(const float* __restrict__ p2, const float* __restrict__ p3,
                    const float* __restrict__ p4, const float* __restrict__ p5,
                    const float* __restrict__ boxes, float* __restrict__ out)
{
    __shared__ float buf[SMEMF];
    __shared__ int s_hs[PH], s_he[PH], s_ws[PH], s_we[PH];

    const int box   = blockIdx.x;
    const int b     = box >> 9;            // N = 512 boxes per batch
    const int cbase = blockIdx.y * CGRP;
    const int tid   = threadIdx.x;

    const float bx1 = __ldg(boxes + 4 * box + 0);
    const float by1 = __ldg(boxes + 4 * box + 1);
    const float bx2 = __ldg(boxes + 4 * box + 2);
    const float by2 = __ldg(boxes + 4 * box + 3);

    // ---- level assignment: floor(4 + log2(sqrt(area)/224 + 1e-8)), clip [2,5]
    // XLA rewrites x/const -> x * (1/const); replicate with rn-mul by f32(1/224).
    // floor(4 + log2(v)) == ilogb(v) + 4 exactly (v > 0, integral shift).
    const float areaf = __fmul_rn(__fsub_rn(bx2, bx1), __fsub_rn(by2, by1));
    const float sq    = __fsqrt_rn(areaf);
    const float v     = __fadd_rn(__fmul_rn(sq, 1.0f / 224.0f), 1e-8f);
    int lvl = ilogbf(v) + 4;
    lvl = min(5, max(2, lvl)) - 2;

    const float* feat;
    int H; float scale;
    switch (lvl) {
        case 0:  feat = p2; H = 200; scale = 0.25f;    break;
        case 1:  feat = p3; H = 100; scale = 0.125f;   break;
        case 2:  feat = p4; H = 50;  scale = 0.0625f;  break;
        default: feat = p5; H = 25;  scale = 0.03125f; break;
    }
    const int W = H;

    // ---- round-half-up box corners at this level (scale = 2^-k: mul exact)
    const int x1 = (int)floorf(__fadd_rn(__fmul_rn(bx1, scale), 0.5f));
    const int y1 = (int)floorf(__fadd_rn(__fmul_rn(by1, scale), 0.5f));
    const int x2 = (int)floorf(__fadd_rn(__fmul_rn(bx2, scale), 0.5f));
    const int y2 = (int)floorf(__fadd_rn(__fmul_rn(by2, scale), 0.5f));

    // XLA: roi/7 -> roi * f32(1/7)  (reciprocal-multiply, NOT div.rn)
    const float bwf = __fmul_rn((float)max(x2 - x1 + 1, 1), 1.0f / 7.0f);
    const float bhf = __fmul_rn((float)max(y2 - y1 + 1, 1), 1.0f / 7.0f);

    // ---- per-bin boundaries (clipped to [0, H]/[0, W]); values always >= 0
    if (tid < PH) {
        s_hs[tid] = min((int)floorf(__fmul_rn((float)tid,       bhf)) + y1, H);
        s_he[tid] = min((int)ceilf (__fmul_rn((float)(tid + 1), bhf)) + y1, H);
    } else if (tid < 2 * PH) {
        const int j = tid - PH;
        s_ws[j] = min((int)floorf(__fmul_rn((float)j,       bwf)) + x1, W);
        s_we[j] = min((int)ceilf (__fmul_rn((float)(j + 1), bwf)) + x1, W);
    }
    __syncthreads();

    // ---- staging region: union of effective bin ranges (monotone in bin idx)
    const int y0   = s_hs[0];
    const int x0   = s_ws[0];
    const int yend = min(s_he[PH - 1], min(s_hs[PH - 1], H - MB) + MB);
    const int xend = min(s_we[PH - 1], min(s_ws[PH - 1], W - MB) + MB);
    const int rh   = max(yend - y0, 0);
    const int rw   = max(xend - x0, 0);
    const int area = rh * rw;

    const size_t HW    = (size_t)H * W;
    const float* bfeat = feat + (size_t)b * NCH * HW;

    const bool direct = (area > SMEMF);   // safety fallback; level assignment bounds area <= ~1100
    const int  CT     = direct ? CGRP : min(CGRP, SMEMF / max(area, 1));
    const int  wid    = tid >> 5;
    const int  lane   = tid & 31;
    const float NEG_INF = __int_as_float(0xff800000u);

    for (int cc = 0; cc < CGRP; cc += CT) {
        const int ctc = min(CT, CGRP - cc);

        // ---- stage ROI region for ctc channels: coalesced along x
        if (!direct && area > 0) {
            for (int ci = 0; ci < ctc; ++ci) {
                const float* pl = bfeat + (size_t)(cbase + cc + ci) * HW
                                        + (size_t)y0 * W + x0;
                float* db = buf + ci * area;
                for (int r = wid; r < rh; r += 8) {
                    const float* src  = pl + (size_t)r * W;
                    float*       drow = db + r * rw;
                    for (int x = lane; x < rw; x += 32)
                        drow[x] = __ldg(src + x);
                }
            }
        }
        __syncthreads();

        // ---- compute ctc*49 bin maxes
        const int ntask = ctc * PP;
        for (int t = tid; t < ntask; t += 256) {
            const int ci  = t / PP;
            const int bin = t - ci * PP;
            const int py  = bin / PH;
            const int px  = bin - py * PH;

            const int rs  = s_hs[py], hev = s_he[py];
            const int cs  = s_ws[px], wev = s_we[px];

            float val = 0.0f;
            if (hev > rs && wev > cs) {
                // effective ranges after MB-bounded dynamic_slice + mask:
                const int re = min(hev, min(rs, H - MB) + MB);
                const int ce = min(wev, min(cs, W - MB) + MB);
                const int nr = re - rs;
                const int nc = ce - cs;
                float m = NEG_INF;
                if (direct) {
                    const float* pl = bfeat + (size_t)(cbase + cc + ci) * HW;
                    for (int r = 0; r < nr; ++r) {
                        const float* row = pl + (size_t)(rs + r) * W + cs;
                        for (int x = 0; x < nc; ++x)
                            m = fmaxf(m, __ldg(row + x));
                    }
                } else {
                    const float* cb = buf + ci * area + (rs - y0) * rw + (cs - x0);
                    for (int r = 0; r < nr; ++r) {
                        const float* row = cb + r * rw;
                        for (int x = 0; x < nc; ++x)
                            m = fmaxf(m, row[x]);
                    }
                }
                val = m;
            }
            out[((size_t)box * NCH + (cbase + cc + ci)) * PP + bin] = val;
        }
        __syncthreads();
    }
}

extern "C" void kernel_launch(void* const* d_in, const int* in_sizes, int n_in,
                              void* d_out, int out_size)
{
    const float *p2 = nullptr, *p3 = nullptr, *p4 = nullptr, *p5 = nullptr;
    const float *boxes = nullptr;

    for (int i = 0; i < n_in; ++i) {
        switch (in_sizes[i]) {
            case 2 * 256 * 200 * 200: p2    = (const float*)d_in[i]; break;
            case 2 * 256 * 100 * 100: p3    = (const float*)d_in[i]; break;
            case 2 * 256 * 50  * 50 : p4    = (const float*)d_in[i]; break;
            case 2 * 256 * 25  * 25 : p5    = (const float*)d_in[i]; break;
            case 2 * 512 * 4        : boxes = (const float*)d_in[i]; break;
            default: break;
        }
    }

    dim3 grid(NBOX, NCH / CGRP);
    roipool_kernel<<<grid, 256>>>(p2, p3, p4, p5, boxes, (float*)d_out);
}

// round 12
// speedup vs baseline: 1.0013x; 1.0013x over previous
#include <cuda_runtime.h>

#define PH    7
#define PP    49          // PH*PH
#define MB    8
#define NCH   256
#define NBOX  1024
#define CGRP  64          // channels per block (grid.y = NCH/CGRP)
#define SMEMF 11776       // 46 KB staging buffer (floats) -- keep static smem < 48 KB

__global__ __launch_bounds__(256)
void roipool_kernel(const float* __restrict__ p2, const float* __restrict__ p3,
                    const float* __restrict__ p4, const float* __restrict__ p5,
                    const float* __restrict__ boxes, float* __restrict__ out)
{
    __shared__ float buf[SMEMF];
    __shared__ int s_hs[PH], s_he[PH], s_ws[PH], s_we[PH];

    const int box   = blockIdx.x;
    const int b     = box >> 9;            // N = 512 boxes per batch
    const int cbase = blockIdx.y * CGRP;
    const int tid   = threadIdx.x;

    const float bx1 = __ldg(boxes + 4 * box + 0);
    const float by1 = __ldg(boxes + 4 * box + 1);
    const float bx2 = __ldg(boxes + 4 * box + 2);
    const float by2 = __ldg(boxes + 4 * box + 3);

    // ---- level assignment: floor(4 + log2(sqrt(area)/224 + 1e-8)), clip [2,5]
    // XLA rewrites x/const -> x * (1/const); replicate with rn-mul by f32(1/224).
    // floor(4 + log2(v)) == ilogb(v) + 4 exactly (v > 0, integral shift).
    const float areaf = __fmul_rn(__fsub_rn(bx2, bx1), __fsub_rn(by2, by1));
    const float sq    = __fsqrt_rn(areaf);
    const float v     = __fadd_rn(__fmul_rn(sq, 1.0f / 224.0f), 1e-8f);
    int lvl = ilogbf(v) + 4;
    lvl = min(5, max(2, lvl)) - 2;

    const float* feat;
    int H; float scale;
    switch (lvl) {
        case 0:  feat = p2; H = 200; scale = 0.25f;    break;
        case 1:  feat = p3; H = 100; scale = 0.125f;   break;
        case 2:  feat = p4; H = 50;  scale = 0.0625f;  break;
        default: feat = p5; H = 25;  scale = 0.03125f; break;
    }
    const int W = H;

    // ---- round-half-up box corners at this level (scale = 2^-k: mul exact)
    const int x1 = (int)floorf(__fadd_rn(__fmul_rn(bx1, scale), 0.5f));
    const int y1 = (int)floorf(__fadd_rn(__fmul_rn(by1, scale), 0.5f));
    const int x2 = (int)floorf(__fadd_rn(__fmul_rn(bx2, scale), 0.5f));
    const int y2 = (int)floorf(__fadd_rn(__fmul_rn(by2, scale), 0.5f));

    // XLA: roi/7 -> roi * f32(1/7)  (reciprocal-multiply, NOT div.rn)
    const float bwf = __fmul_rn((float)max(x2 - x1 + 1, 1), 1.0f / 7.0f);
    const float bhf = __fmul_rn((float)max(y2 - y1 + 1, 1), 1.0f / 7.0f);

    // ---- per-bin boundaries (clipped to [0, H]/[0, W]); values always >= 0
    if (tid < PH) {
        s_hs[tid] = min((int)floorf(__fmul_rn((float)tid,       bhf)) + y1, H);
        s_he[tid] = min((int)ceilf (__fmul_rn((float)(tid + 1), bhf)) + y1, H);
    } else if (tid < 2 * PH) {
        const int j = tid - PH;
        s_ws[j] = min((int)floorf(__fmul_rn((float)j,       bwf)) + x1, W);
        s_we[j] = min((int)ceilf (__fmul_rn((float)(j + 1), bwf)) + x1, W);
    }
    __syncthreads();

    // ---- staging region: union of effective bin ranges (monotone in bin idx)
    const int y0   = s_hs[0];
    const int x0   = s_ws[0];
    const int yend = min(s_he[PH - 1], min(s_hs[PH - 1], H - MB) + MB);
    const int xend = min(s_we[PH - 1], min(s_ws[PH - 1], W - MB) + MB);
    const int rh   = max(yend - y0, 0);
    const int rw   = max(xend - x0, 0);
    const int area = rh * rw;

    const size_t HW    = (size_t)H * W;
    const float* bfeat = feat + (size_t)b * NCH * HW;

    const bool direct = (area > SMEMF);   // safety fallback; level assignment bounds area <= ~1100
    const int  CT     = direct ? CGRP : min(CGRP, SMEMF / max(area, 1));
    const int  wid    = tid >> 5;
    const int  lane   = tid & 31;
    const float NEG_INF = __int_as_float(0xff800000u);

    for (int cc = 0; cc < CGRP; cc += CT) {
        const int ctc = min(CT, CGRP - cc);

        // ---- stage ROI region for ctc channels: coalesced along x
        if (!direct && area > 0) {
            for (int ci = 0; ci < ctc; ++ci) {
                const float* pl = bfeat + (size_t)(cbase + cc + ci) * HW
                                        + (size_t)y0 * W + x0;
                float* db = buf + ci * area;
                for (int r = wid; r < rh; r += 8) {
                    const float* src  = pl + (size_t)r * W;
                    float*       drow = db + r * rw;
                    for (int x = lane; x < rw; x += 32)
                        drow[x] = __ldg(src + x);
                }
            }
        }
        __syncthreads();

        // ---- compute ctc*49 bin maxes
        const int ntask = ctc * PP;
        for (int t = tid; t < ntask; t += 256) {
            const int ci  = t / PP;
            const int bin = t - ci * PP;
            const int py  = bin / PH;
            const int px  = bin - py * PH;

            const int rs  = s_hs[py], hev = s_he[py];
            const int cs  = s_ws[px], wev = s_we[px];

            float val = 0.0f;
            if (hev > rs && wev > cs) {
                // effective ranges after MB-bounded dynamic_slice + mask:
                const int re = min(hev, min(rs, H - MB) + MB);
                const int ce = min(wev, min(cs, W - MB) + MB);
                const int nr = re - rs;
                const int nc = ce - cs;
                float m = NEG_INF;
                if (direct) {
                    const float* pl = bfeat + (size_t)(cbase + cc + ci) * HW;
                    for (int r = 0; r < nr; ++r) {
                        const float* row = pl + (size_t)(rs + r) * W + cs;
                        for (int x = 0; x < nc; ++x)
                            m = fmaxf(m, __ldg(row + x));
                    }
                } else {
                    const float* cb = buf + ci * area + (rs - y0) * rw + (cs - x0);
                    for (int r = 0; r < nr; ++r) {
                        const float* row = cb + r * rw;
                        for (int x = 0; x < nc; ++x)
                            m = fmaxf(m, row[x]);
                    }
                }
                val = m;
            }
            out[((size_t)box * NCH + (cbase + cc + ci)) * PP + bin] = val;
        }
        __syncthreads();
    }
}

extern "C" void kernel_launch(void* const* d_in, const int* in_sizes, int n_in,
                              void* d_out, int out_size)
{
    const float *p2 = nullptr, *p3 = nullptr, *p4 = nullptr, *p5 = nullptr;
    const float *boxes = nullptr;

    for (int i = 0; i < n_in; ++i) {
        switch (in_sizes[i]) {
            case 2 * 256 * 200 * 200: p2    = (const float*)d_in[i]; break;
            case 2 * 256 * 100 * 100: p3    = (const float*)d_in[i]; break;
            case 2 * 256 * 50  * 50 : p4    = (const float*)d_in[i]; break;
            case 2 * 256 * 25  * 25 : p5    = (const float*)d_in[i]; break;
            case 2 * 512 * 4        : boxes = (const float*)d_in[i]; break;
            default: break;
        }
    }

    dim3 grid(NBOX, NCH / CGRP);
    roipool_kernel<<<grid, 256>>>(p2, p3, p4, p5, boxes, (float*)d_out);
}

// round 13
// speedup vs baseline: 1.0046x; 1.0033x over previous
#include <cuda_runtime.h>

#define PH    7
#define PP    49          // PH*PH
#define MB    8
#define NCH   256
#define NBOX  1024
#define CGRP  64          // channels per block (grid.y = NCH/CGRP)
#define SMEMF 11776       // 46 KB staging buffer (floats) -- keep static smem < 48 KB

__global__ __launch_bounds__(256)
void roipool_kernel(const float* __restrict__ p2, const float* __restrict__ p3,
                    const float* __restrict__ p4, const float* __restrict__ p5,
                    const float* __restrict__ boxes, float* __restrict__ out)
{
    __shared__ float buf[SMEMF];
    __shared__ int s_hs[PH], s_he[PH], s_ws[PH], s_we[PH];

    const int box   = blockIdx.x;
    const int b     = box >> 9;            // N = 512 boxes per batch
    const int cbase = blockIdx.y * CGRP;
    const int tid   = threadIdx.x;

    const float bx1 = __ldg(boxes + 4 * box + 0);
    const float by1 = __ldg(boxes + 4 * box + 1);
    const float bx2 = __ldg(boxes + 4 * box + 2);
    const float by2 = __ldg(boxes + 4 * box + 3);

    // ---- level assignment: floor(4 + log2(sqrt(area)/224 + 1e-8)), clip [2,5]
    // XLA rewrites x/const -> x * (1/const); replicate with rn-mul by f32(1/224).
    // floor(4 + log2(v)) == ilogb(v) + 4 exactly (v > 0, integral shift).
    const float areaf = __fmul_rn(__fsub_rn(bx2, bx1), __fsub_rn(by2, by1));
    const float sq    = __fsqrt_rn(areaf);
    const float v     = __fadd_rn(__fmul_rn(sq, 1.0f / 224.0f), 1e-8f);
    int lvl = ilogbf(v) + 4;
    lvl = min(5, max(2, lvl)) - 2;

    const float* feat;
    int H; float scale;
    switch (lvl) {
        case 0:  feat = p2; H = 200; scale = 0.25f;    break;
        case 1:  feat = p3; H = 100; scale = 0.125f;   break;
        case 2:  feat = p4; H = 50;  scale = 0.0625f;  break;
        default: feat = p5; H = 25;  scale = 0.03125f; break;
    }
    const int W = H;

    // ---- round-half-up box corners at this level (scale = 2^-k: mul exact)
    const int x1 = (int)floorf(__fadd_rn(__fmul_rn(bx1, scale), 0.5f));
    const int y1 = (int)floorf(__fadd_rn(__fmul_rn(by1, scale), 0.5f));
    const int x2 = (int)floorf(__fadd_rn(__fmul_rn(bx2, scale), 0.5f));
    const int y2 = (int)floorf(__fadd_rn(__fmul_rn(by2, scale), 0.5f));

    // XLA: roi/7 -> roi * f32(1/7)  (reciprocal-multiply, NOT div.rn)
    const float bwf = __fmul_rn((float)max(x2 - x1 + 1, 1), 1.0f / 7.0f);
    const float bhf = __fmul_rn((float)max(y2 - y1 + 1, 1), 1.0f / 7.0f);

    // ---- per-bin boundaries (clipped to [0, H]/[0, W]); values always >= 0
    if (tid < PH) {
        s_hs[tid] = min((int)floorf(__fmul_rn((float)tid,       bhf)) + y1, H);
        s_he[tid] = min((int)ceilf (__fmul_rn((float)(tid + 1), bhf)) + y1, H);
    } else if (tid < 2 * PH) {
        const int j = tid - PH;
        s_ws[j] = min((int)floorf(__fmul_rn((float)j,       bwf)) + x1, W);
        s_we[j] = min((int)ceilf (__fmul_rn((float)(j + 1), bwf)) + x1, W);
    }
    __syncthreads();

    // ---- staging region: union of effective bin ranges (monotone in bin idx)
    const int y0   = s_hs[0];
    const int x0   = s_ws[0];
    const int yend = min(s_he[PH - 1], min(s_hs[PH - 1], H - MB) + MB);
    const int xend = min(s_we[PH - 1], min(s_ws[PH - 1], W - MB) + MB);
    const int rh   = max(yend - y0, 0);
    const int rw   = max(xend - x0, 0);
    const int area = rh * rw;

    const size_t HW    = (size_t)H * W;
    const float* bfeat = feat + (size_t)b * NCH * HW;

    const bool direct = (area > SMEMF);   // safety fallback; level assignment bounds area <= ~1100
    const int  CT     = direct ? CGRP : min(CGRP, SMEMF / max(area, 1));
    const int  wid    = tid >> 5;
    const int  lane   = tid & 31;
    const float NEG_INF = __int_as_float(0xff800000u);

    for (int cc = 0; cc < CGRP; cc += CT) {
        const int ctc = min(CT, CGRP - cc);

        // ---- stage ROI region for ctc channels: coalesced along x
        if (!direct && area > 0) {
            for (int ci = 0; ci < ctc; ++ci) {
                const float* pl = bfeat + (size_t)(cbase + cc + ci) * HW
                                        + (size_t)y0 * W + x0;
                float* db = buf + ci * area;
                for (int r = wid; r < rh; r += 8) {
                    const float* src  = pl + (size_t)r * W;
                    float*       drow = db + r * rw;
                    for (int x = lane; x < rw; x += 32)
                        drow[x] = __ldg(src + x);
                }
            }
        }
        __syncthreads();

        // ---- compute ctc*49 bin maxes
        const int ntask = ctc * PP;
        for (int t = tid; t < ntask; t += 256) {
            const int ci  = t / PP;
            const int bin = t - ci * PP;
            const int py  = bin / PH;
            const int px  = bin - py * PH;

            const int rs  = s_hs[py], hev = s_he[py];
            const int cs  = s_ws[px], wev = s_we[px];

            float val = 0.0f;
            if (hev > rs && wev > cs) {
                // effective ranges after MB-bounded dynamic_slice + mask:
                const int re = min(hev, min(rs, H - MB) + MB);
                const int ce = min(wev, min(cs, W - MB) + MB);
                const int nr = re - rs;
                const int nc = ce - cs;
                float m = NEG_INF;
                if (direct) {
                    const float* pl = bfeat + (size_t)(cbase + cc + ci) * HW;
                    for (int r = 0; r < nr; ++r) {
                        const float* row = pl + (size_t)(rs + r) * W + cs;
                        for (int x = 0; x < nc; ++x)
                            m = fmaxf(m, __ldg(row + x));
                    }
                } else {
                    const float* cb = buf + ci * area + (rs - y0) * rw + (cs - x0);
                    for (int r = 0; r < nr; ++r) {
                        const float* row = cb + r * rw;
                        for (int x = 0; x < nc; ++x)
                            m = fmaxf(m, row[x]);
                    }
                }
                val = m;
            }
            out[((size_t)box * NCH + (cbase + cc + ci)) * PP + bin] = val;
        }
        __syncthreads();
    }
}

extern "C" void kernel_launch(void* const* d_in, const int* in_sizes, int n_in,
                              void* d_out, int out_size)
{
    const float *p2 = nullptr, *p3 = nullptr, *p4 = nullptr, *p5 = nullptr;
    const float *boxes = nullptr;

    for (int i = 0; i < n_in; ++i) {
        switch (in_sizes[i]) {
            case 2 * 256 * 200 * 200: p2    = (const float*)d_in[i]; break;
            case 2 * 256 * 100 * 100: p3    = (const float*)d_in[i]; break;
            case 2 * 256 * 50  * 50 : p4    = (const float*)d_in[i]; break;
            case 2 * 256 * 25  * 25 : p5    = (const float*)d_in[i]; break;
            case 2 * 512 * 4        : boxes = (const float*)d_in[i]; break;
            default: break;
        }
    }

    dim3 grid(NBOX, NCH / CGRP);
    roipool_kernel<<<grid, 256>>>(p2, p3, p4, p5, boxes, (float*)d_out);
}